// round 2
// baseline (speedup 1.0000x reference)
#include <cuda_runtime.h>
#include <math.h>

#define BB 16
#define MM 60
#define TT 80
#define NA 128
#define NP 20
#define NL 64
#define NLP (NL*NP)      // 1280 lane points
#define NAP (NA/2)       // 64 agent pairs
#define NLPP (NLP/2)     // 640 lane pairs
#define NTHR 160
#define NBLK (BB*MM)     // 960

__device__ float g_partial[BB*MM];
__device__ int   g_count;          // zero-init; reset by last block each launch

typedef unsigned long long ull;

__device__ __forceinline__ ull pk2(float lo, float hi){
    ull r; asm("mov.b64 %0, {%1,%2};" : "=l"(r) : "f"(lo), "f"(hi)); return r;
}
__device__ __forceinline__ float2 up2(ull v){
    float2 r; asm("mov.b64 {%0,%1}, %2;" : "=f"(r.x), "=f"(r.y) : "l"(v)); return r;
}
__device__ __forceinline__ ull add2(ull a, ull b){
    ull d; asm("add.rn.f32x2 %0, %1, %2;" : "=l"(d) : "l"(a), "l"(b)); return d;
}
__device__ __forceinline__ ull mul2(ull a, ull b){
    ull d; asm("mul.rn.f32x2 %0, %1, %2;" : "=l"(d) : "l"(a), "l"(b)); return d;
}
__device__ __forceinline__ ull fma2_(ull a, ull b, ull c){
    ull d; asm("fma.rn.f32x2 %0, %1, %2, %3;" : "=l"(d) : "l"(a), "l"(b), "l"(c)); return d;
}

__global__ __launch_bounds__(NTHR) void fused_kernel(
    const float* __restrict__ mode_logits,
    const float* __restrict__ all_trajs,
    const float* __restrict__ agents_now,
    const float* __restrict__ agents_mask,
    const float* __restrict__ map_lanes,
    const float* __restrict__ lanes_mask,
    float* __restrict__ out,
    int write_idx)
{
    // Pairs stored NEGATED: (-x0,-x1,-y0,-y1) so dx = ex + (-px) (bit-identical to ex-px)
    __shared__ float4 s_ag[NAP];
    __shared__ float4 s_ln[NLPP];
    __shared__ float  s_jerk[TT-3];
    __shared__ int    s_coll, s_undr, s_last;

    const int bm  = blockIdx.x;
    const int b   = bm / MM;
    const int tid = threadIdx.x;           // 0..159

    if (tid == 0){ s_coll = 0; s_undr = 0; }

    // ── Stage agents (negated xy); invalid -> far away (same effect as +BIG penalty)
    for (int i = tid; i < NA; i += NTHR){
        float valid = agents_mask[b*NA + i];
        float ax = agents_now[(b*NA + i)*4 + 0];
        float ay = agents_now[(b*NA + i)*4 + 1];
        if (valid == 0.0f){ ax = 1e18f; ay = 0.0f; }
        float* p = (float*)&s_ag[i>>1];
        p[(i&1)]     = -ax;
        p[2+(i&1)]   = -ay;
    }
    // ── Stage lane points (mask repeats per point, jnp.repeat(mask, P))
    for (int j = tid; j < NLP; j += NTHR){
        float valid = lanes_mask[b*NL + j/NP];
        const float* src = map_lanes + ((size_t)b*NLP + j)*3;
        float x = src[0], y = src[1];
        if (valid == 0.0f){ x = 1e18f; y = 0.0f; }
        float* p = (float*)&s_ln[j>>1];
        p[(j&1)]     = -x;
        p[2+(j&1)]   = -y;
    }

    const float* traj = all_trajs + (size_t)bm * TT * 3;

    // ── Comfort: jerk[t] = x[t+3]-3x[t+2]+3x[t+1]-x[t]
    if (tid < TT-3){
        int t = tid;
        float jx = traj[(t+3)*3+0] - 3.0f*traj[(t+2)*3+0] + 3.0f*traj[(t+1)*3+0] - traj[t*3+0];
        float jy = traj[(t+3)*3+1] - 3.0f*traj[(t+2)*3+1] + 3.0f*traj[(t+1)*3+1] - traj[t*3+1];
        s_jerk[t] = sqrtf(jx*jx + jy*jy);
    }
    __syncthreads();

    // ── Distance tests: 2 threads per timestep, packed f32x2 (2 points/iter)
    const int t = tid >> 1;
    const int q = tid & 1;
    const float ex = traj[t*3+0];
    const float ey = traj[t*3+1];
    const ull EX = pk2(ex, ex);
    const ull EY = pk2(ey, ey);

    float m0 = 3.4e38f, m1 = 3.4e38f;        // agent sqdist mins (even/odd)
    float n0 = 3.4e38f, n1 = 3.4e38f;        // lane  sqdist mins

    #pragma unroll 8
    for (int p = q; p < NAP; p += 2){
        float4 v = s_ag[p];
        ull DX = add2(EX, pk2(v.x, v.y));
        ull DY = add2(EY, pk2(v.z, v.w));
        ull D2 = fma2_(DX, DX, mul2(DY, DY));
        float2 d = up2(D2);
        m0 = fminf(m0, d.x);
        m1 = fminf(m1, d.y);
    }
    #pragma unroll 8
    for (int p = q; p < NLPP; p += 2){
        float4 v = s_ln[p];
        ull DX = add2(EX, pk2(v.x, v.y));
        ull DY = add2(EY, pk2(v.z, v.w));
        ull D2 = fma2_(DX, DX, mul2(DY, DY));
        float2 d = up2(D2);
        n0 = fminf(n0, d.x);
        n1 = fminf(n1, d.y);
    }

    float mina = fminf(m0, m1);
    float minl = fminf(n0, n1);
    mina = fminf(mina, __shfl_xor_sync(0xffffffffu, mina, 1));
    minl = fminf(minl, __shfl_xor_sync(0xffffffffu, minl, 1));

    if (q == 0){
        if (mina < 4.0f) atomicAdd(&s_coll, 1);   // min_dist < 2.0
        if (minl > 9.0f) atomicAdd(&s_undr, 1);   // min_lane_dist > 3.0
    }
    __syncthreads();

    if (tid == 0){
        float js = 0.0f;
        for (int i = 0; i < TT-3; i++) js += s_jerk[i];     // fixed order
        float comfort   = -js / (float)(TT-3);
        float progress  = traj[(TT-1)*3 + 0];
        float collision = -(float)s_coll / (float)TT;
        float drivable  = -(float)s_undr / (float)TT;
        g_partial[bm] = 0.1f*comfort + 0.5f*progress + 1.0f*collision + 0.3f*drivable;
    }

    // ── Last-block-done: fuse selection (kills the second launch)
    if (tid == 0){
        __threadfence();
        int c = atomicAdd(&g_count, 1);
        s_last = (c == NBLK-1);
        if (s_last) g_count = 0;                 // reset for next graph replay
    }
    __syncthreads();
    if (!s_last) return;
    __threadfence();

    // Selection: 5 warps, warp w handles b = w, w+5, w+10, w+15
    const int w = tid >> 5, lane = tid & 31;
    for (int r = 0; r < 4; r++){
        int bb = w + 5*r;
        if (bb >= BB) break;

        float l0 = mode_logits[bb*MM + lane];                                  // m = lane (<32<60)
        float l1 = (lane < MM-32) ? mode_logits[bb*MM + 32 + lane] : -3.4e38f; // m = lane+32

        float mx = fmaxf(l0, l1);
        #pragma unroll
        for (int d = 16; d; d >>= 1) mx = fmaxf(mx, __shfl_xor_sync(0xffffffffu, mx, d));

        float e0 = __expf(l0 - mx);
        float e1 = (lane < MM-32) ? __expf(l1 - mx) : 0.0f;
        float sum = e0 + e1;
        #pragma unroll
        for (int d = 16; d; d >>= 1) sum += __shfl_xor_sync(0xffffffffu, sum, d);
        sum = __shfl_sync(0xffffffffu, sum, 0);   // lane-0 association == R1's shared tree

        float s0 = e0/sum + g_partial[bb*MM + lane];
        float s1 = (lane < MM-32) ? e1/sum + g_partial[bb*MM + 32 + lane] : -3.4e38f;

        float bs; int bi;
        if (s1 > s0){ bs = s1; bi = lane + 32; } else { bs = s0; bi = lane; }
        #pragma unroll
        for (int d = 16; d; d >>= 1){
            float ov = __shfl_xor_sync(0xffffffffu, bs, d);
            int   oi = __shfl_xor_sync(0xffffffffu, bi, d);
            if (ov > bs || (ov == bs && oi < bi)){ bs = ov; bi = oi; }
        }
        int sel = __shfl_sync(0xffffffffu, bi, 0);   // first-max (jnp.argmax tie-break)

        const float* src = all_trajs + (size_t)(bb*MM + sel)*TT*3;
        for (int i = lane; i < TT*3; i += 32)
            out[bb*TT*3 + i] = src[i];
        if (lane == 0 && write_idx) out[BB*TT*3 + bb] = (float)sel;
    }
}

extern "C" void kernel_launch(void* const* d_in, const int* in_sizes, int n_in,
                              void* d_out, int out_size)
{
    const float* mode_logits    = (const float*)d_in[0];
    const float* all_trajs      = (const float*)d_in[1];
    const float* agents_now     = (const float*)d_in[2];
    const float* agents_mask    = (const float*)d_in[3];
    const float* map_lanes      = (const float*)d_in[4];
    const float* map_lanes_mask = (const float*)d_in[5];
    float* out = (float*)d_out;

    int write_idx = (out_size >= BB*TT*3 + BB) ? 1 : 0;

    fused_kernel<<<NBLK, NTHR>>>(mode_logits, all_trajs, agents_now, agents_mask,
                                 map_lanes, map_lanes_mask, out, write_idx);
}

// round 3
// speedup vs baseline: 1.5379x; 1.5379x over previous
#include <cuda_runtime.h>
#include <math.h>

#define BB 16
#define MM 60
#define TT 80
#define NA 128
#define NL 64
#define NP 20
#define NTHR 96
#define NBLK (BB*MM)     // 960

__device__ float g_partial[BB*MM];
__device__ int   g_count;          // zero-init; last block resets each launch

__global__ __launch_bounds__(NTHR) void fused_kernel(
    const float* __restrict__ mode_logits,
    const float* __restrict__ all_trajs,
    const float* __restrict__ agents_now,
    const float* __restrict__ agents_mask,
    const float* __restrict__ map_lanes,
    const float* __restrict__ lanes_mask,
    float* __restrict__ out,
    int write_idx)
{
    __shared__ float s_jerk[TT-3];
    __shared__ int   s_cc[3], s_uc[3];
    __shared__ int   s_last;

    const int bm   = blockIdx.x;
    const int b    = bm / MM;
    const int tid  = threadIdx.x;        // 0..95
    const int w    = tid >> 5;           // warp 0..2
    const int lane = tid & 31;

    const float* traj = all_trajs + (size_t)bm * TT * 3;

    // ── Comfort: jerk[t] = x[t+3]-3x[t+2]+3x[t+1]-x[t]  (bitwise same as R1)
    if (tid < TT-3){
        int t = tid;
        float jx = traj[(t+3)*3+0] - 3.0f*traj[(t+2)*3+0] + 3.0f*traj[(t+1)*3+0] - traj[t*3+0];
        float jy = traj[(t+3)*3+1] - 3.0f*traj[(t+2)*3+1] + 3.0f*traj[(t+1)*3+1] - traj[t*3+1];
        s_jerk[t] = sqrtf(jx*jx + jy*jy);
    }

    // ── Boolean distance tests with early exit (witness search).
    bool coll = false;     // exists agent with d2 < 4      (min_dist < 2)
    bool near = false;     // exists lane point with d2 <= 9 (min_lane <= 3)
    if (tid < TT){
        const int t = tid;
        const float ex = traj[t*3+0];
        const float ey = traj[t*3+1];

        // Agents: chunk of 4 for load overlap; exact same d2 test as R1.
        const int bA = b * NA;
        #pragma unroll 1
        for (int i0 = 0; i0 < NA && !coll; i0 += 4){
            #pragma unroll
            for (int k = 0; k < 4; k++){
                int i = bA + i0 + k;
                float m  = agents_mask[i];
                float dx = ex - agents_now[i*4 + 0];
                float dy = ey - agents_now[i*4 + 1];
                if (m != 0.0f && fmaf(dx, dx, dy*dy) < 4.0f) coll = true;
            }
        }

        // Lane points: per-lane mask hoisted, chunk of 4 points.
        const int bL = b * NL;
        #pragma unroll 1
        for (int l = 0; l < NL && !near; l++){
            if (lanes_mask[bL + l] == 0.0f) continue;
            const float* lp = map_lanes + (size_t)(bL + l) * NP * 3;
            #pragma unroll 1
            for (int p = 0; p < NP && !near; p += 4){
                #pragma unroll
                for (int k = 0; k < 4; k++){
                    float dx = ex - lp[(p+k)*3 + 0];
                    float dy = ey - lp[(p+k)*3 + 1];
                    if (fmaf(dx, dx, dy*dy) <= 9.0f) near = true;
                }
            }
        }
    }

    // Count per warp (all 32 lanes converged here; t>=80 lanes contribute false).
    unsigned cb = __ballot_sync(0xffffffffu, coll);
    unsigned ub = __ballot_sync(0xffffffffu, !near && (tid < TT));  // undrivable
    if (lane == 0){ s_cc[w] = __popc(cb); s_uc[w] = __popc(ub); }
    __syncthreads();

    if (tid == 0){
        float js = 0.0f;
        for (int i = 0; i < TT-3; i++) js += s_jerk[i];    // fixed order
        int cc = s_cc[0] + s_cc[1] + s_cc[2];
        int uc = s_uc[0] + s_uc[1] + s_uc[2];
        float comfort   = -js / (float)(TT-3);
        float progress  = traj[(TT-1)*3 + 0];
        float collision = -(float)cc / (float)TT;
        float drivable  = -(float)uc / (float)TT;
        g_partial[bm] = 0.1f*comfort + 0.5f*progress + 1.0f*collision + 0.3f*drivable;
    }

    // ── Last-block-done: fused selection (single launch total)
    if (tid == 0){
        __threadfence();
        int c = atomicAdd(&g_count, 1);
        s_last = (c == NBLK-1);
        if (s_last) g_count = 0;                  // reset for graph replay
    }
    __syncthreads();
    if (!s_last) return;
    __threadfence();

    // 3 warps; warp w handles bb = w, w+3, ..., <16
    for (int r = 0; r < 6; r++){
        int bb = w + 3*r;
        if (bb >= BB) break;

        float l0 = mode_logits[bb*MM + lane];                                   // m = lane
        float l1 = (lane < MM-32) ? mode_logits[bb*MM + 32 + lane] : -3.4e38f;  // m = lane+32

        float mx = fmaxf(l0, l1);
        #pragma unroll
        for (int d = 16; d; d >>= 1) mx = fmaxf(mx, __shfl_xor_sync(0xffffffffu, mx, d));

        float e0 = __expf(l0 - mx);
        float e1 = (lane < MM-32) ? __expf(l1 - mx) : 0.0f;
        float sum = e0 + e1;
        #pragma unroll
        for (int d = 16; d; d >>= 1) sum += __shfl_xor_sync(0xffffffffu, sum, d);
        sum = __shfl_sync(0xffffffffu, sum, 0);

        float s0 = e0/sum + g_partial[bb*MM + lane];
        float s1 = (lane < MM-32) ? e1/sum + g_partial[bb*MM + 32 + lane] : -3.4e38f;

        float bs; int bi;
        if (s1 > s0){ bs = s1; bi = lane + 32; } else { bs = s0; bi = lane; }
        #pragma unroll
        for (int d = 16; d; d >>= 1){
            float ov = __shfl_xor_sync(0xffffffffu, bs, d);
            int   oi = __shfl_xor_sync(0xffffffffu, bi, d);
            if (ov > bs || (ov == bs && oi < bi)){ bs = ov; bi = oi; }
        }
        int sel = __shfl_sync(0xffffffffu, bi, 0);    // first-max tie-break

        const float* src = all_trajs + (size_t)(bb*MM + sel)*TT*3;
        for (int i = lane; i < TT*3; i += 32)
            out[bb*TT*3 + i] = src[i];
        if (lane == 0 && write_idx) out[BB*TT*3 + bb] = (float)sel;
    }
}

extern "C" void kernel_launch(void* const* d_in, const int* in_sizes, int n_in,
                              void* d_out, int out_size)
{
    const float* mode_logits    = (const float*)d_in[0];
    const float* all_trajs      = (const float*)d_in[1];
    const float* agents_now     = (const float*)d_in[2];
    const float* agents_mask    = (const float*)d_in[3];
    const float* map_lanes      = (const float*)d_in[4];
    const float* map_lanes_mask = (const float*)d_in[5];
    float* out = (float*)d_out;

    int write_idx = (out_size >= BB*TT*3 + BB) ? 1 : 0;

    fused_kernel<<<NBLK, NTHR>>>(mode_logits, all_trajs, agents_now, agents_mask,
                                 map_lanes, map_lanes_mask, out, write_idx);
}

// round 4
// speedup vs baseline: 1.8595x; 1.2092x over previous
#include <cuda_runtime.h>
#include <math.h>

#define BB 16
#define MM 60
#define TT 80
#define NA 128
#define NL 64
#define NP 20
#define NLP (NL*NP)      // 1280
#define NTHR 96
#define NBLK (BB*MM)     // 960
#define CH 16            // scan chunk size

__device__ float g_partial[BB*MM];
__device__ int   g_count;          // zero-init; last block resets each launch

__global__ __launch_bounds__(NTHR) void fused_kernel(
    const float* __restrict__ mode_logits,
    const float* __restrict__ all_trajs,
    const float* __restrict__ agents_now,
    const float* __restrict__ agents_mask,
    const float* __restrict__ map_lanes,
    const float* __restrict__ lanes_mask,
    float* __restrict__ out,
    int write_idx)
{
    __shared__ float2 s_ag[NA];
    __shared__ float2 s_ln[NLP];
    __shared__ float  s_jerk[TT-3];
    __shared__ int    s_cc[3], s_uc[3];
    __shared__ int    s_last;

    const int bm   = blockIdx.x;
    const int b    = bm / MM;
    const int tid  = threadIdx.x;        // 0..95
    const int w    = tid >> 5;
    const int lane = tid & 31;

    const float* traj = all_trajs + (size_t)bm * TT * 3;

    // ── Stage agents; invalid -> far away (identical effect to +BIG penalty)
    for (int i = tid; i < NA; i += NTHR){
        float valid = agents_mask[b*NA + i];
        float ax = agents_now[(b*NA + i)*4 + 0];
        float ay = agents_now[(b*NA + i)*4 + 1];
        if (valid == 0.0f){ ax = 1e18f; ay = 0.0f; }
        s_ag[i] = make_float2(ax, ay);
    }
    // ── Stage lane points (mask repeats per point)
    for (int j = tid; j < NLP; j += NTHR){
        float valid = lanes_mask[b*NL + j/NP];
        const float* src = map_lanes + ((size_t)b*NLP + j)*3;
        float x = src[0], y = src[1];
        if (valid == 0.0f){ x = 1e18f; y = 0.0f; }
        s_ln[j] = make_float2(x, y);
    }

    // ── Comfort: jerk[t] = x[t+3]-3x[t+2]+3x[t+1]-x[t]  (bitwise same as R1)
    if (tid < TT-3){
        int t = tid;
        float jx = traj[(t+3)*3+0] - 3.0f*traj[(t+2)*3+0] + 3.0f*traj[(t+1)*3+0] - traj[t*3+0];
        float jy = traj[(t+3)*3+1] - 3.0f*traj[(t+2)*3+1] + 3.0f*traj[(t+1)*3+1] - traj[t*3+1];
        s_jerk[t] = sqrtf(jx*jx + jy*jy);
    }
    __syncthreads();

    // ── Boolean tests: chunked early-exit scans over shared memory.
    bool coll = false;     // exists agent with d2 < 4       (min_dist < 2)
    bool near = false;     // exists lane point with d2 <= 9 (min_lane <= 3)
    if (tid < TT){
        const int t = tid;
        const float ex = traj[t*3+0];
        const float ey = traj[t*3+1];

        #pragma unroll 1
        for (int c = 0; c < NA; c += CH){
            float mn = 3.4e38f;
            #pragma unroll
            for (int k = 0; k < CH; k++){
                float2 p = s_ag[c+k];
                float dx = ex - p.x, dy = ey - p.y;
                mn = fminf(mn, fmaf(dx, dx, dy*dy));
            }
            if (mn < 4.0f){ coll = true; break; }
        }

        #pragma unroll 1
        for (int c = 0; c < NLP; c += CH){
            float mn = 3.4e38f;
            #pragma unroll
            for (int k = 0; k < CH; k++){
                float2 p = s_ln[c+k];
                float dx = ex - p.x, dy = ey - p.y;
                mn = fminf(mn, fmaf(dx, dx, dy*dy));
            }
            if (mn <= 9.0f){ near = true; break; }
        }
    }

    unsigned cb = __ballot_sync(0xffffffffu, coll);
    unsigned ub = __ballot_sync(0xffffffffu, !near && (tid < TT));
    if (lane == 0){ s_cc[w] = __popc(cb); s_uc[w] = __popc(ub); }
    __syncthreads();

    if (tid == 0){
        float js = 0.0f;
        for (int i = 0; i < TT-3; i++) js += s_jerk[i];    // fixed order
        int cc = s_cc[0] + s_cc[1] + s_cc[2];
        int uc = s_uc[0] + s_uc[1] + s_uc[2];
        float comfort   = -js / (float)(TT-3);
        float progress  = traj[(TT-1)*3 + 0];
        float collision = -(float)cc / (float)TT;
        float drivable  = -(float)uc / (float)TT;
        g_partial[bm] = 0.1f*comfort + 0.5f*progress + 1.0f*collision + 0.3f*drivable;
    }

    // ── Last-block-done: fused selection (single launch total)
    if (tid == 0){
        __threadfence();
        int c = atomicAdd(&g_count, 1);
        s_last = (c == NBLK-1);
        if (s_last) g_count = 0;                  // reset for graph replay
    }
    __syncthreads();
    if (!s_last) return;
    __threadfence();

    // 3 warps; warp w handles bb = w, w+3, ..., <16
    for (int r = 0; r < 6; r++){
        int bb = w + 3*r;
        if (bb >= BB) break;

        float l0 = mode_logits[bb*MM + lane];                                   // m = lane
        float l1 = (lane < MM-32) ? mode_logits[bb*MM + 32 + lane] : -3.4e38f;  // m = lane+32

        float mx = fmaxf(l0, l1);
        #pragma unroll
        for (int d = 16; d; d >>= 1) mx = fmaxf(mx, __shfl_xor_sync(0xffffffffu, mx, d));

        float e0 = __expf(l0 - mx);
        float e1 = (lane < MM-32) ? __expf(l1 - mx) : 0.0f;
        float sum = e0 + e1;
        #pragma unroll
        for (int d = 16; d; d >>= 1) sum += __shfl_xor_sync(0xffffffffu, sum, d);
        sum = __shfl_sync(0xffffffffu, sum, 0);

        float s0 = e0/sum + g_partial[bb*MM + lane];
        float s1 = (lane < MM-32) ? e1/sum + g_partial[bb*MM + 32 + lane] : -3.4e38f;

        float bs; int bi;
        if (s1 > s0){ bs = s1; bi = lane + 32; } else { bs = s0; bi = lane; }
        #pragma unroll
        for (int d = 16; d; d >>= 1){
            float ov = __shfl_xor_sync(0xffffffffu, bs, d);
            int   oi = __shfl_xor_sync(0xffffffffu, bi, d);
            if (ov > bs || (ov == bs && oi < bi)){ bs = ov; bi = oi; }
        }
        int sel = __shfl_sync(0xffffffffu, bi, 0);    // first-max tie-break

        const float* src = all_trajs + (size_t)(bb*MM + sel)*TT*3;
        for (int i = lane; i < TT*3; i += 32)
            out[bb*TT*3 + i] = src[i];
        if (lane == 0 && write_idx) out[BB*TT*3 + bb] = (float)sel;
    }
}

extern "C" void kernel_launch(void* const* d_in, const int* in_sizes, int n_in,
                              void* d_out, int out_size)
{
    const float* mode_logits    = (const float*)d_in[0];
    const float* all_trajs      = (const float*)d_in[1];
    const float* agents_now     = (const float*)d_in[2];
    const float* agents_mask    = (const float*)d_in[3];
    const float* map_lanes      = (const float*)d_in[4];
    const float* map_lanes_mask = (const float*)d_in[5];
    float* out = (float*)d_out;

    int write_idx = (out_size >= BB*TT*3 + BB) ? 1 : 0;

    fused_kernel<<<NBLK, NTHR>>>(mode_logits, all_trajs, agents_now, agents_mask,
                                 map_lanes, map_lanes_mask, out, write_idx);
}

// round 5
// speedup vs baseline: 2.5805x; 1.3877x over previous
#include <cuda_runtime.h>
#include <math.h>

#define BB 16
#define MM 60
#define TT 80
#define NA 128
#define NL 64
#define NP 20
#define NLP (NL*NP)        // 1280
#define NTHR 1024
#define CH 16              // scan chunk size
#define NJ (MM*(TT-3))     // 4620 jerk tasks
#define NDT (MM*TT)        // 4800 distance tasks

__global__ __launch_bounds__(NTHR) void fused_kernel(
    const float* __restrict__ mode_logits,
    const float* __restrict__ all_trajs,
    const float* __restrict__ agents_now,
    const float* __restrict__ agents_mask,
    const float* __restrict__ map_lanes,
    const float* __restrict__ lanes_mask,
    float* __restrict__ out,
    int write_idx)
{
    __shared__ float2 s_ag[NA];        // 1 KB
    __shared__ float2 s_ln[NLP];       // 10.25 KB
    __shared__ float  s_jerk[NJ];      // 18.5 KB
    __shared__ int    s_cc[MM], s_uc[MM];
    __shared__ float  s_part[MM];
    __shared__ int    s_sel;

    const int b    = blockIdx.x;
    const int tid  = threadIdx.x;      // 0..1023
    const int lane = tid & 31;

    if (tid < MM){ s_cc[tid] = 0; s_uc[tid] = 0; }

    // ── Stage agents once per batch; invalid -> far away (== +BIG penalty)
    for (int i = tid; i < NA; i += NTHR){
        float valid = agents_mask[b*NA + i];
        float ax = agents_now[(b*NA + i)*4 + 0];
        float ay = agents_now[(b*NA + i)*4 + 1];
        if (valid == 0.0f){ ax = 1e18f; ay = 0.0f; }
        s_ag[i] = make_float2(ax, ay);
    }
    // ── Stage lane points once (mask repeats per point)
    for (int j = tid; j < NLP; j += NTHR){
        float valid = lanes_mask[b*NL + j/NP];
        const float* src = map_lanes + ((size_t)b*NLP + j)*3;
        float x = src[0], y = src[1];
        if (valid == 0.0f){ x = 1e18f; y = 0.0f; }
        s_ln[j] = make_float2(x, y);
    }

    const float* trajb = all_trajs + (size_t)b * MM * TT * 3;

    // ── All jerk norms for this batch (same formula as before, bit-exact)
    for (int j = tid; j < NJ; j += NTHR){
        int m = j / (TT-3), t = j - m*(TT-3);
        const float* tr = trajb + (m*TT + t)*3;
        float jx = tr[9]  - 3.0f*tr[6] + 3.0f*tr[3] - tr[0];
        float jy = tr[10] - 3.0f*tr[7] + 3.0f*tr[4] - tr[1];
        s_jerk[j] = sqrtf(jx*jx + jy*jy);
    }
    __syncthreads();

    // ── Distance tasks: task j = (m, t), ego index == j. Prefetch next ego.
    {
        float nex = 0.0f, ney = 0.0f;
        if (tid < NDT){ nex = trajb[tid*3]; ney = trajb[tid*3 + 1]; }
        for (int j = tid; j < NDT; j += NTHR){
            const float ex = nex, ey = ney;
            int jn = j + NTHR;
            if (jn < NDT){ nex = trajb[jn*3]; ney = trajb[jn*3 + 1]; }
            const int m = j / TT;

            bool coll = false;   // exists agent with d2 < 4       (min_dist < 2)
            bool near = false;   // exists lane point with d2 <= 9 (min_lane <= 3)

            #pragma unroll 1
            for (int c = 0; c < NA; c += CH){
                float mn = 3.4e38f;
                #pragma unroll
                for (int k = 0; k < CH; k++){
                    float2 p = s_ag[c+k];
                    float dx = ex - p.x, dy = ey - p.y;
                    mn = fminf(mn, fmaf(dx, dx, dy*dy));
                }
                if (mn < 4.0f){ coll = true; break; }
            }
            #pragma unroll 1
            for (int c = 0; c < NLP; c += CH){
                float mn = 3.4e38f;
                #pragma unroll
                for (int k = 0; k < CH; k++){
                    float2 p = s_ln[c+k];
                    float dx = ex - p.x, dy = ey - p.y;
                    mn = fminf(mn, fmaf(dx, dx, dy*dy));
                }
                if (mn <= 9.0f){ near = true; break; }
            }

            if (coll)  atomicAdd(&s_cc[m], 1);   // integer -> deterministic
            if (!near) atomicAdd(&s_uc[m], 1);
        }
    }
    __syncthreads();

    // ── Per-mode partial score; jerk summed serially in fixed order (bit-exact)
    if (tid < MM){
        const int m = tid;
        float js = 0.0f;
        const int base = m * (TT-3);
        for (int i = 0; i < TT-3; i++) js += s_jerk[base + i];
        float comfort   = -js / (float)(TT-3);
        float progress  = trajb[(m*TT + TT-1)*3];
        float collision = -(float)s_cc[m] / (float)TT;
        float drivable  = -(float)s_uc[m] / (float)TT;
        s_part[m] = 0.1f*comfort + 0.5f*progress + 1.0f*collision + 0.3f*drivable;
    }
    __syncthreads();

    // ── Selection (warp 0): softmax + first-max argmax, same math as R4
    if (tid < 32){
        float l0 = mode_logits[b*MM + lane];                                   // m = lane
        float l1 = (lane < MM-32) ? mode_logits[b*MM + 32 + lane] : -3.4e38f;  // m = lane+32

        float mx = fmaxf(l0, l1);
        #pragma unroll
        for (int d = 16; d; d >>= 1) mx = fmaxf(mx, __shfl_xor_sync(0xffffffffu, mx, d));

        float e0 = __expf(l0 - mx);
        float e1 = (lane < MM-32) ? __expf(l1 - mx) : 0.0f;
        float sum = e0 + e1;
        #pragma unroll
        for (int d = 16; d; d >>= 1) sum += __shfl_xor_sync(0xffffffffu, sum, d);
        sum = __shfl_sync(0xffffffffu, sum, 0);

        float s0 = e0/sum + s_part[lane];
        float s1 = (lane < MM-32) ? e1/sum + s_part[32 + lane] : -3.4e38f;

        float bs; int bi;
        if (s1 > s0){ bs = s1; bi = lane + 32; } else { bs = s0; bi = lane; }
        #pragma unroll
        for (int d = 16; d; d >>= 1){
            float ov = __shfl_xor_sync(0xffffffffu, bs, d);
            int   oi = __shfl_xor_sync(0xffffffffu, bi, d);
            if (ov > bs || (ov == bs && oi < bi)){ bs = ov; bi = oi; }
        }
        if (lane == 0) s_sel = bi;     // first-max (jnp.argmax tie-break)
    }
    __syncthreads();

    // ── Emit selected trajectory (+ index)
    const int sel = s_sel;
    const float* src = trajb + (size_t)(sel*TT)*3;
    if (tid < TT*3) out[b*TT*3 + tid] = src[tid];
    if (tid == 0 && write_idx) out[BB*TT*3 + b] = (float)sel;
}

extern "C" void kernel_launch(void* const* d_in, const int* in_sizes, int n_in,
                              void* d_out, int out_size)
{
    const float* mode_logits    = (const float*)d_in[0];
    const float* all_trajs      = (const float*)d_in[1];
    const float* agents_now     = (const float*)d_in[2];
    const float* agents_mask    = (const float*)d_in[3];
    const float* map_lanes      = (const float*)d_in[4];
    const float* map_lanes_mask = (const float*)d_in[5];
    float* out = (float*)d_out;

    int write_idx = (out_size >= BB*TT*3 + BB) ? 1 : 0;

    fused_kernel<<<BB, NTHR>>>(mode_logits, all_trajs, agents_now, agents_mask,
                               map_lanes, map_lanes_mask, out, write_idx);
}

// round 6
// speedup vs baseline: 3.0450x; 1.1800x over previous
#include <cuda_runtime.h>
#include <math.h>

#define BB 16
#define MM 60
#define TT 80
#define NA 128
#define NL 64
#define NP 20
#define NLP (NL*NP)        // 1280
#define NTHR 1024
#define MPB 15             // modes per block
#define SPB 4              // blocks (slices) per batch
#define NDT (MPB*TT)       // 1200 distance tasks per block
#define BIGF 3.4e38f

__device__ float g_partial[BB*MM];
__device__ int   g_sync[BB];        // zero-init; selector resets each launch

__global__ __launch_bounds__(NTHR) void fused_kernel(
    const float* __restrict__ mode_logits,
    const float* __restrict__ all_trajs,
    const float* __restrict__ agents_now,
    const float* __restrict__ agents_mask,
    const float* __restrict__ map_lanes,
    const float* __restrict__ lanes_mask,
    float* __restrict__ out,
    int write_idx)
{
    __shared__ __align__(16) float2 s_ag[NA];    // 1 KB
    __shared__ __align__(16) float2 s_ln[NLP];   // 10.25 KB
    __shared__ int   s_cc[MPB], s_uc[MPB];
    __shared__ int   s_last, s_sel;

    const int blk  = blockIdx.x;
    const int b    = blk >> 2;          // batch
    const int m0   = (blk & 3) * MPB;   // first mode of this slice
    const int tid  = threadIdx.x;
    const int w    = tid >> 5;
    const int lane = tid & 31;

    if (tid < MPB){ s_cc[tid] = 0; s_uc[tid] = 0; }

    // ── Stage agents; invalid -> far away (== +BIG penalty semantics)
    for (int i = tid; i < NA; i += NTHR){
        float valid = agents_mask[b*NA + i];
        float ax = agents_now[(b*NA + i)*4 + 0];
        float ay = agents_now[(b*NA + i)*4 + 1];
        if (valid == 0.0f){ ax = 1e18f; ay = 0.0f; }
        s_ag[i] = make_float2(ax, ay);
    }
    // ── Stage lane points (mask repeats per point)
    for (int j = tid; j < NLP; j += NTHR){
        float valid = lanes_mask[b*NL + j/NP];
        const float* src = map_lanes + ((size_t)b*NLP + j)*3;
        float x = src[0], y = src[1];
        if (valid == 0.0f){ x = 1e18f; y = 0.0f; }
        s_ln[j] = make_float2(x, y);
    }
    __syncthreads();

    const float* trajb = all_trajs + (size_t)b * MM * TT * 3;
    const float4* pa = (const float4*)s_ag;      // 2 points per float4
    const float4* pl = (const float4*)s_ln;

    // ── Distance tasks for this slice: j = (m-m0)*TT + t
    for (int j = tid; j < NDT; j += NTHR){
        const int ml = j / TT;               // local mode 0..14
        const int t  = j - ml*TT;
        const int m  = m0 + ml;
        const float ex = trajb[(m*TT + t)*3 + 0];
        const float ey = trajb[(m*TT + t)*3 + 1];

        bool coll = false;    // exists agent with d2 < 4       (min_dist < 2)
        bool near = false;    // exists lane point with d2 <= 9 (min_lane <= 3)

        float a0 = BIGF, a1 = BIGF;
        #pragma unroll 1
        for (int c = 0; c < NA/2; c += 4){   // 8 points per chunk
            #pragma unroll
            for (int k = 0; k < 4; k++){
                float4 p = pa[c+k];
                float dx0 = ex - p.x, dy0 = ey - p.y;
                float dx1 = ex - p.z, dy1 = ey - p.w;
                a0 = fminf(a0, fmaf(dx0, dx0, dy0*dy0));
                a1 = fminf(a1, fmaf(dx1, dx1, dy1*dy1));
            }
            if (fminf(a0, a1) < 4.0f){ coll = true; break; }
        }

        float n0 = BIGF, n1 = BIGF;
        #pragma unroll 1
        for (int c = 0; c < NLP/2; c += 4){
            #pragma unroll
            for (int k = 0; k < 4; k++){
                float4 p = pl[c+k];
                float dx0 = ex - p.x, dy0 = ey - p.y;
                float dx1 = ex - p.z, dy1 = ey - p.w;
                n0 = fminf(n0, fmaf(dx0, dx0, dy0*dy0));
                n1 = fminf(n1, fmaf(dx1, dx1, dy1*dy1));
            }
            if (fminf(n0, n1) <= 9.0f){ near = true; break; }
        }

        if (coll)  atomicAdd(&s_cc[ml], 1);   // integer -> deterministic
        if (!near) atomicAdd(&s_uc[ml], 1);
    }
    __syncthreads();

    // ── One warp per mode: jerk sum + partial score -> global
    if (w < MPB){
        const int m = m0 + w;
        float js = 0.0f;
        for (int t = lane; t < TT-3; t += 32){
            const float* tr = trajb + (m*TT + t)*3;
            float jx = tr[9]  - 3.0f*tr[6] + 3.0f*tr[3] - tr[0];
            float jy = tr[10] - 3.0f*tr[7] + 3.0f*tr[4] - tr[1];
            js += sqrtf(jx*jx + jy*jy);
        }
        #pragma unroll
        for (int d = 16; d; d >>= 1) js += __shfl_xor_sync(0xffffffffu, js, d);

        if (lane == 0){
            float comfort   = -js / (float)(TT-3);
            float progress  = trajb[(m*TT + TT-1)*3];
            float collision = -(float)s_cc[w] / (float)TT;
            float drivable  = -(float)s_uc[w] / (float)TT;
            g_partial[b*MM + m] = 0.1f*comfort + 0.5f*progress
                                + 1.0f*collision + 0.3f*drivable;
            __threadfence();                 // publish before counter bump
        }
    }
    __syncthreads();

    // ── Per-batch handshake: 4th arriving slice does the selection
    if (tid == 0){
        int c = atomicAdd(&g_sync[b], 1);
        s_last = (c == SPB-1);
    }
    __syncthreads();
    if (!s_last) return;
    __threadfence();                         // acquire partials

    // ── Selection (warp 0): softmax + first-max argmax
    if (tid < 32){
        float l0 = mode_logits[b*MM + lane];                                   // m = lane
        float l1 = (lane < MM-32) ? mode_logits[b*MM + 32 + lane] : -BIGF;     // m = lane+32

        float mx = fmaxf(l0, l1);
        #pragma unroll
        for (int d = 16; d; d >>= 1) mx = fmaxf(mx, __shfl_xor_sync(0xffffffffu, mx, d));

        float e0 = __expf(l0 - mx);
        float e1 = (lane < MM-32) ? __expf(l1 - mx) : 0.0f;
        float sum = e0 + e1;
        #pragma unroll
        for (int d = 16; d; d >>= 1) sum += __shfl_xor_sync(0xffffffffu, sum, d);
        sum = __shfl_sync(0xffffffffu, sum, 0);

        float s0 = e0/sum + g_partial[b*MM + lane];
        float s1 = (lane < MM-32) ? e1/sum + g_partial[b*MM + 32 + lane] : -BIGF;

        float bs; int bi;
        if (s1 > s0){ bs = s1; bi = lane + 32; } else { bs = s0; bi = lane; }
        #pragma unroll
        for (int d = 16; d; d >>= 1){
            float ov = __shfl_xor_sync(0xffffffffu, bs, d);
            int   oi = __shfl_xor_sync(0xffffffffu, bi, d);
            if (ov > bs || (ov == bs && oi < bi)){ bs = ov; bi = oi; }
        }
        if (lane == 0) s_sel = bi;           // first-max (jnp.argmax tie-break)
    }
    __syncthreads();

    // ── Emit selected trajectory (+ index), reset counter for graph replay
    const int sel = s_sel;
    const float* src = trajb + (size_t)(sel*TT)*3;
    if (tid < TT*3) out[b*TT*3 + tid] = src[tid];
    if (tid == 0){
        if (write_idx) out[BB*TT*3 + b] = (float)sel;
        g_sync[b] = 0;
    }
}

extern "C" void kernel_launch(void* const* d_in, const int* in_sizes, int n_in,
                              void* d_out, int out_size)
{
    const float* mode_logits    = (const float*)d_in[0];
    const float* all_trajs      = (const float*)d_in[1];
    const float* agents_now     = (const float*)d_in[2];
    const float* agents_mask    = (const float*)d_in[3];
    const float* map_lanes      = (const float*)d_in[4];
    const float* map_lanes_mask = (const float*)d_in[5];
    float* out = (float*)d_out;

    int write_idx = (out_size >= BB*TT*3 + BB) ? 1 : 0;

    fused_kernel<<<BB*SPB, NTHR>>>(mode_logits, all_trajs, agents_now, agents_mask,
                                   map_lanes, map_lanes_mask, out, write_idx);
}

// round 7
// speedup vs baseline: 3.6467x; 1.1976x over previous
#include <cuda_runtime.h>
#include <math.h>

#define BB 16
#define MM 60
#define TT 80
#define NA 128
#define NL 64
#define NP 20
#define NLP (NL*NP)        // 1280
#define NTHR 1024
#define SPB 8              // slices (blocks) per batch
#define BIGF 3.4e38f

__device__ float g_partial[BB*MM];
__device__ int   g_sync[BB];        // zero-init; selector resets each launch

__global__ __launch_bounds__(NTHR) void fused_kernel(
    const float* __restrict__ mode_logits,
    const float* __restrict__ all_trajs,
    const float* __restrict__ agents_now,
    const float* __restrict__ agents_mask,
    const float* __restrict__ map_lanes,
    const float* __restrict__ lanes_mask,
    float* __restrict__ out,
    int write_idx)
{
    __shared__ __align__(16) float2 s_ag[NA];
    __shared__ __align__(16) float2 s_ln[NLP];
    __shared__ int  s_cc[8], s_uc[8];
    __shared__ int  s_last, s_sel;

    const int blk  = blockIdx.x;
    const int b    = blk >> 3;                    // batch
    const int s    = blk & 7;                     // slice
    const int MPB  = (s < 4) ? 8 : 7;             // modes in this slice
    const int m0   = (s < 4) ? s*8 : 32 + (s-4)*7;
    const int NDT  = MPB * TT;                    // 560 or 640 tasks
    const int tid  = threadIdx.x;
    const int w    = tid >> 5;
    const int lane = tid & 31;

    if (tid < 8){ s_cc[tid] = 0; s_uc[tid] = 0; }

    const float* trajb = all_trajs + (size_t)b * MM * TT * 3;

    // ── Ego prefetch (before barrier; overlaps with staging latency)
    float ex = 0.0f, ey = 0.0f;
    if (tid < NDT){
        const float* p = trajb + (size_t)(m0*TT + tid)*3;   // task j==tid, ego idx m0*TT+tid
        ex = p[0]; ey = p[1];
    }

    // ── Stage agents; invalid -> far away (== +BIG penalty semantics)
    for (int i = tid; i < NA; i += NTHR){
        float valid = agents_mask[b*NA + i];
        float ax = agents_now[(b*NA + i)*4 + 0];
        float ay = agents_now[(b*NA + i)*4 + 1];
        if (valid == 0.0f){ ax = 1e18f; ay = 0.0f; }
        s_ag[i] = make_float2(ax, ay);
    }
    // ── Stage lane points (mask repeats per point)
    for (int j = tid; j < NLP; j += NTHR){
        float valid = lanes_mask[b*NL + j/NP];
        const float* src = map_lanes + ((size_t)b*NLP + j)*3;
        float x = src[0], y = src[1];
        if (valid == 0.0f){ x = 1e18f; y = 0.0f; }
        s_ln[j] = make_float2(x, y);
    }
    __syncthreads();

    const float4* pa = (const float4*)s_ag;   // 2 points per float4
    const float4* pl = (const float4*)s_ln;

    // ── Warps 0..19: distance tasks (one per thread).
    //    Warps 20..27: jerk sums, fully overlapped (global-only).
    float js = 0.0f;                          // jerk warp partial
    if (tid < NDT){
        const int ml = tid / TT;              // local mode

        bool coll = false;   // exists agent with d2 < 4       (min_dist < 2)
        bool near = false;   // exists lane point with d2 <= 9 (min_lane <= 3)

        float a0 = BIGF, a1 = BIGF;
        #pragma unroll 1
        for (int c = 0; c < NA/2; c += 4){    // 8 points per chunk
            #pragma unroll
            for (int k = 0; k < 4; k++){
                float4 p = pa[c+k];
                float dx0 = ex - p.x, dy0 = ey - p.y;
                float dx1 = ex - p.z, dy1 = ey - p.w;
                a0 = fminf(a0, fmaf(dx0, dx0, dy0*dy0));
                a1 = fminf(a1, fmaf(dx1, dx1, dy1*dy1));
            }
            if (fminf(a0, a1) < 4.0f){ coll = true; break; }
        }

        float n0 = BIGF, n1 = BIGF;
        #pragma unroll 1
        for (int c = 0; c < NLP/2; c += 4){
            #pragma unroll
            for (int k = 0; k < 4; k++){
                float4 p = pl[c+k];
                float dx0 = ex - p.x, dy0 = ey - p.y;
                float dx1 = ex - p.z, dy1 = ey - p.w;
                n0 = fminf(n0, fmaf(dx0, dx0, dy0*dy0));
                n1 = fminf(n1, fmaf(dx1, dx1, dy1*dy1));
            }
            if (fminf(n0, n1) <= 9.0f){ near = true; break; }
        }

        if (coll)  atomicAdd(&s_cc[ml], 1);   // integer -> deterministic
        if (!near) atomicAdd(&s_uc[ml], 1);
    }
    else if (w >= 20 && w < 20 + MPB){
        const int m = m0 + (w - 20);
        for (int t = lane; t < TT-3; t += 32){
            const float* tr = trajb + (size_t)(m*TT + t)*3;
            float jx = tr[9]  - 3.0f*tr[6] + 3.0f*tr[3] - tr[0];
            float jy = tr[10] - 3.0f*tr[7] + 3.0f*tr[4] - tr[1];
            js += sqrtf(jx*jx + jy*jy);
        }
        #pragma unroll
        for (int d = 16; d; d >>= 1) js += __shfl_xor_sync(0xffffffffu, js, d);
    }
    __syncthreads();

    // ── Publish partial scores for this slice
    if (w >= 20 && w < 20 + MPB && lane == 0){
        const int ml = w - 20;
        const int m  = m0 + ml;
        float comfort   = -js / (float)(TT-3);
        float progress  = trajb[(size_t)(m*TT + TT-1)*3];
        float collision = -(float)s_cc[ml] / (float)TT;
        float drivable  = -(float)s_uc[ml] / (float)TT;
        g_partial[b*MM + m] = 0.1f*comfort + 0.5f*progress
                            + 1.0f*collision + 0.3f*drivable;
        __threadfence();                      // publish before counter bump
    }
    __syncthreads();

    // ── Per-batch handshake: 8th arriving slice selects
    if (tid == 0){
        int c = atomicAdd(&g_sync[b], 1);
        s_last = (c == SPB-1);
    }
    __syncthreads();
    if (!s_last) return;
    __threadfence();                          // acquire other slices' partials

    // ── Selection (warp 0): softmax + first-max argmax
    if (tid < 32){
        float l0 = mode_logits[b*MM + lane];                                  // m = lane
        float l1 = (lane < MM-32) ? mode_logits[b*MM + 32 + lane] : -BIGF;    // m = lane+32

        float mx = fmaxf(l0, l1);
        #pragma unroll
        for (int d = 16; d; d >>= 1) mx = fmaxf(mx, __shfl_xor_sync(0xffffffffu, mx, d));

        float e0 = __expf(l0 - mx);
        float e1 = (lane < MM-32) ? __expf(l1 - mx) : 0.0f;
        float sum = e0 + e1;
        #pragma unroll
        for (int d = 16; d; d >>= 1) sum += __shfl_xor_sync(0xffffffffu, sum, d);
        sum = __shfl_sync(0xffffffffu, sum, 0);

        float sc0 = e0/sum + g_partial[b*MM + lane];
        float sc1 = (lane < MM-32) ? e1/sum + g_partial[b*MM + 32 + lane] : -BIGF;

        float bs; int bi;
        if (sc1 > sc0){ bs = sc1; bi = lane + 32; } else { bs = sc0; bi = lane; }
        #pragma unroll
        for (int d = 16; d; d >>= 1){
            float ov = __shfl_xor_sync(0xffffffffu, bs, d);
            int   oi = __shfl_xor_sync(0xffffffffu, bi, d);
            if (ov > bs || (ov == bs && oi < bi)){ bs = ov; bi = oi; }
        }
        if (lane == 0) s_sel = bi;            // first-max (jnp.argmax tie-break)
    }
    __syncthreads();

    // ── Emit selected trajectory (+ index), reset counter for graph replay
    const int sel = s_sel;
    const float* src = trajb + (size_t)(sel*TT)*3;
    if (tid < TT*3) out[b*TT*3 + tid] = src[tid];
    if (tid == 0){
        if (write_idx) out[BB*TT*3 + b] = (float)sel;
        g_sync[b] = 0;
    }
}

extern "C" void kernel_launch(void* const* d_in, const int* in_sizes, int n_in,
                              void* d_out, int out_size)
{
    const float* mode_logits    = (const float*)d_in[0];
    const float* all_trajs      = (const float*)d_in[1];
    const float* agents_now     = (const float*)d_in[2];
    const float* agents_mask    = (const float*)d_in[3];
    const float* map_lanes      = (const float*)d_in[4];
    const float* map_lanes_mask = (const float*)d_in[5];
    float* out = (float*)d_out;

    int write_idx = (out_size >= BB*TT*3 + BB) ? 1 : 0;

    fused_kernel<<<BB*SPB, NTHR>>>(mode_logits, all_trajs, agents_now, agents_mask,
                                   map_lanes, map_lanes_mask, out, write_idx);
}